// round 5
// baseline (speedup 1.0000x reference)
#include <cuda_runtime.h>

#define NUM_USERS 50000
#define NUM_ITEMS 50000
#define D 64
#define DV 16                       // float4 chunks per 64-float node row
#define N_NODES (NUM_USERS + NUM_ITEMS)
#define N_EDGES 500000
#define NNZ_G 1000000
#define NNZ_GX 2000000
#define N_GXE (NNZ_GX * 2)          // endpoint contributions (user+item halves)
#define BATCH 8192

// ---- static device scratch (no allocation allowed) ----
__device__ float g_A[(size_t)N_NODES * D];    // current node embeddings
__device__ float g_B[(size_t)N_NODES * D];    // G * A (post g-spmm)
__device__ float g_acc[(size_t)N_NODES * D];  // sum of per-layer embeddings
__device__ float g_deg[N_NODES];

// CSR-by-destination for the fused edge pipeline (gx), built once per call
__device__ int  g_cnt[N_NODES];
__device__ int  g_off[N_NODES + 1];
__device__ int  g_cur[N_NODES];
__device__ int2 g_gxe[N_GXE];                 // {src | cidx<<17 | half<<26, val bits}

// CSR-by-destination for the node-graph spmm (g), built once per call
__device__ int  g_gcnt[N_NODES];
__device__ int  g_goff[N_NODES + 1];
__device__ int  g_gcur[N_NODES];
__device__ int2 g_ge[NNZ_G];                  // {src, val bits}

// init: A = concat(user_emb, item_emb), acc = 0, deg/cnt/gcnt = 0
__global__ void k_init(const float* __restrict__ ue, const float* __restrict__ ie) {
    int t = blockIdx.x * blockDim.x + threadIdx.x;
    if (t >= N_NODES * DV) return;
    float4 v;
    if (t < NUM_USERS * DV) v = ((const float4*)ue)[t];
    else                    v = ((const float4*)ie)[t - NUM_USERS * DV];
    ((float4*)g_A)[t]   = v;
    ((float4*)g_acc)[t] = make_float4(0.f, 0.f, 0.f, 0.f);
    if (t < N_NODES) { g_deg[t] = 0.f; g_cnt[t] = 0; g_gcnt[t] = 0; }
}

// degree = bincount(train_users) + bincount(50000 + train_items)
__global__ void k_deg(const int* __restrict__ tu, const int* __restrict__ ti) {
    int e = blockIdx.x * blockDim.x + threadIdx.x;
    if (e >= N_EDGES) return;
    atomicAdd(&g_deg[tu[e]], 1.f);
    atomicAdd(&g_deg[NUM_USERS + ti[e]], 1.f);
}

// count gx endpoint contributions per destination node
__global__ void k_count_gx(const int* __restrict__ gxr,
                           const int* __restrict__ tu, const int* __restrict__ ti) {
    int e = blockIdx.x * blockDim.x + threadIdx.x;
    if (e >= NNZ_GX) return;
    int r = gxr[e];
    atomicAdd(&g_cnt[tu[r]], 1);
    atomicAdd(&g_cnt[NUM_USERS + ti[r]], 1);
}

// count g nnz per destination row
__global__ void k_count_g(const int* __restrict__ rows) {
    int e = blockIdx.x * blockDim.x + threadIdx.x;
    if (e >= NNZ_G) return;
    atomicAdd(&g_gcnt[rows[e]], 1);
}

// single-block exclusive scan: off[0..n] from cnt[0..n-1]; cur := off
__global__ void k_scan(const int* __restrict__ cnt, int* __restrict__ off,
                       int* __restrict__ cur, int n) {
    __shared__ int ssum[1024];
    int tid = threadIdx.x;
    int chunk = (n + 1023) / 1024;
    int beg = tid * chunk;
    int end = beg + chunk; if (end > n) end = n; if (beg > n) beg = n;
    int s = 0;
    for (int i = beg; i < end; ++i) s += cnt[i];
    ssum[tid] = s;
    __syncthreads();
    for (int o = 1; o < 1024; o <<= 1) {
        int v = (tid >= o) ? ssum[tid - o] : 0;
        __syncthreads();
        ssum[tid] += v;
        __syncthreads();
    }
    int run = (tid == 0) ? 0 : ssum[tid - 1];
    for (int i = beg; i < end; ++i) {
        int c = cnt[i];
        off[i] = run;
        cur[i] = run;
        run += c;
    }
    if (tid == 1023) off[n] = ssum[1023];
}

// scatter gx contributions into destination-sorted entry array
__global__ void k_scatter_gx(const int* __restrict__ gxr, const int* __restrict__ gxc,
                             const float* __restrict__ gxv,
                             const int* __restrict__ tu, const int* __restrict__ ti,
                             const int* __restrict__ i2c) {
    int e = blockIdx.x * blockDim.x + threadIdx.x;
    if (e >= NNZ_GX) return;
    int r = gxr[e], c = gxc[e];
    int du = tu[r];
    int di = NUM_USERS + ti[r];
    int su = tu[c];
    int tic = ti[c];
    int si = NUM_USERS + tic;
    int cidx = i2c[tic];
    int vb = __float_as_int(gxv[e]);
    int pu = atomicAdd(&g_cur[du], 1);
    g_gxe[pu] = make_int2(su | (cidx << 17), vb);
    int pi = atomicAdd(&g_cur[di], 1);
    g_gxe[pi] = make_int2(si | (cidx << 17) | (1 << 26), vb);
}

// scatter g nnz into destination-sorted entry array
__global__ void k_scatter_g(const int* __restrict__ rows, const int* __restrict__ cols,
                            const float* __restrict__ vals) {
    int e = blockIdx.x * blockDim.x + threadIdx.x;
    if (e >= NNZ_G) return;
    int p = atomicAdd(&g_gcur[rows[e]], 1);
    g_ge[p] = make_int2(cols[e], __float_as_int(vals[e]));
}

// pull-mode node spmm: B[n] = sum_{e in seg(n)} v_e * A[src_e]
__global__ void __launch_bounds__(256) k_spmm_pull() {
    int t = blockIdx.x * blockDim.x + threadIdx.x;
    if (t >= N_NODES * DV) return;
    int n = t >> 4, j = t & 15;
    int beg = g_goff[n], end = g_goff[n + 1];
    const float4* Av = (const float4*)g_A;
    float4 acc = make_float4(0.f, 0.f, 0.f, 0.f);
    for (int i = beg; i < end; ++i) {
        int2 e = g_ge[i];
        float v = __int_as_float(e.y);
        float4 x = Av[e.x * DV + j];
        acc.x += v * x.x; acc.y += v * x.y; acc.z += v * x.z; acc.w += v * x.w;
    }
    ((float4*)g_B)[t] = acc;
}

// pull-mode fused edge pipeline + combine:
//   U[n] = sum_{e in seg(n)} v_e * (B[src_e] (+ cat[cidx_e, half] on layer 0))
//   A[n] = 0.5 * (U[n]/(deg[n]+1e-9) + B[n]);  acc += A
template <int LAYER0>
__global__ void __launch_bounds__(256) k_gx_pull(const float* __restrict__ cat) {
    int t = blockIdx.x * blockDim.x + threadIdx.x;
    if (t >= N_NODES * DV) return;
    int n = t >> 4, j = t & 15;
    int beg = g_off[n], end = g_off[n + 1];
    const float4* Bv = (const float4*)g_B;
    const float4* catv = (const float4*)cat;
    int coff = ((n >= NUM_USERS) ? 16 : 0) + j;   // cat half select
    float4 acc = make_float4(0.f, 0.f, 0.f, 0.f);
    for (int i = beg; i < end; ++i) {
        int2 e = g_gxe[i];
        float v = __int_as_float(e.y);
        int src = e.x & 0x1FFFF;
        float4 x = Bv[src * DV + j];
        if (LAYER0) {
            int cidx = (e.x >> 17) & 0x1FF;
            float4 c = catv[cidx * 32 + coff];
            x.x += c.x; x.y += c.y; x.z += c.z; x.w += c.w;
        }
        acc.x += v * x.x; acc.y += v * x.y; acc.z += v * x.z; acc.w += v * x.w;
    }
    float inv = 0.5f / (g_deg[n] + 1e-9f);
    float4 b = Bv[t];
    float4 a;
    a.x = acc.x * inv + 0.5f * b.x;
    a.y = acc.y * inv + 0.5f * b.y;
    a.z = acc.z * inv + 0.5f * b.z;
    a.w = acc.w * inv + 0.5f * b.w;
    ((float4*)g_A)[t] = a;
    float4 ac = ((float4*)g_acc)[t];
    ac.x += a.x; ac.y += a.y; ac.z += a.z; ac.w += a.w;
    ((float4*)g_acc)[t] = ac;
}

// gamma[b] = dot(acc[users[b]], acc[50000+items[b]]) / 9   (mean over 3 layers)
__global__ void k_dot(const int* __restrict__ users, const int* __restrict__ items,
                      float* __restrict__ out) {
    int t = blockIdx.x * blockDim.x + threadIdx.x;
    int b = t >> 5;
    if (b >= BATCH) return;
    int lane = t & 31;
    const float2* au = (const float2*)(g_acc + (size_t)users[b] * D);
    const float2* ai = (const float2*)(g_acc + (size_t)(NUM_USERS + items[b]) * D);
    float2 x = au[lane], y = ai[lane];
    float s = x.x * y.x + x.y * y.y;
    #pragma unroll
    for (int o = 16; o; o >>= 1) s += __shfl_down_sync(0xffffffffu, s, o);
    if (lane == 0) out[b] = s * (1.f / 9.f);
}

extern "C" void kernel_launch(void* const* d_in, const int* in_sizes, int n_in,
                              void* d_out, int out_size) {
    const float* user_emb = (const float*)d_in[0];
    const float* item_emb = (const float*)d_in[1];
    const float* cat_emb  = (const float*)d_in[2];
    const float* g_vals   = (const float*)d_in[3];
    const float* gx_vals  = (const float*)d_in[4];
    const int*   g_rows   = (const int*)d_in[5];
    const int*   g_cols   = (const int*)d_in[6];
    const int*   gx_rows  = (const int*)d_in[7];
    const int*   gx_cols  = (const int*)d_in[8];
    const int*   tu       = (const int*)d_in[9];
    const int*   ti       = (const int*)d_in[10];
    const int*   i2c      = (const int*)d_in[11];
    const int*   users    = (const int*)d_in[12];
    const int*   items    = (const int*)d_in[13];
    float* out = (float*)d_out;

    const int TB = 256;
    int node_grid = (N_NODES * DV + TB - 1) / TB;        // 6250
    int deg_grid  = (N_EDGES + TB - 1) / TB;             // 1954
    int gx_grid   = (NNZ_GX + TB - 1) / TB;              // 7813
    int g_grid    = (NNZ_G + TB - 1) / TB;               // 3907
    int dot_grid  = (BATCH * 32 + TB - 1) / TB;          // 1024

    // device-symbol addresses are host-visible via cudaGetSymbolAddress-free
    // direct launches; kernels reference the symbols internally.
    int *cnt_p, *off_p, *cur_p, *gcnt_p, *goff_p, *gcur_p;
    cudaGetSymbolAddress((void**)&cnt_p,  g_cnt);
    cudaGetSymbolAddress((void**)&off_p,  g_off);
    cudaGetSymbolAddress((void**)&cur_p,  g_cur);
    cudaGetSymbolAddress((void**)&gcnt_p, g_gcnt);
    cudaGetSymbolAddress((void**)&goff_p, g_goff);
    cudaGetSymbolAddress((void**)&gcur_p, g_gcur);

    k_init<<<node_grid, TB>>>(user_emb, item_emb);
    k_deg<<<deg_grid, TB>>>(tu, ti);
    k_count_gx<<<gx_grid, TB>>>(gx_rows, tu, ti);
    k_count_g<<<g_grid, TB>>>(g_rows);
    k_scan<<<1, 1024>>>(cnt_p,  off_p,  cur_p,  N_NODES);
    k_scan<<<1, 1024>>>(gcnt_p, goff_p, gcur_p, N_NODES);
    k_scatter_gx<<<gx_grid, TB>>>(gx_rows, gx_cols, gx_vals, tu, ti, i2c);
    k_scatter_g<<<g_grid, TB>>>(g_rows, g_cols, g_vals);

    for (int L = 0; L < 3; ++L) {
        k_spmm_pull<<<node_grid, TB>>>();
        if (L == 0) k_gx_pull<1><<<node_grid, TB>>>(cat_emb);
        else        k_gx_pull<0><<<node_grid, TB>>>(cat_emb);
    }
    k_dot<<<dot_grid, TB>>>(users, items, out);
}

// round 7
// speedup vs baseline: 1.0105x; 1.0105x over previous
#include <cuda_runtime.h>

#define NUM_USERS 50000
#define NUM_ITEMS 50000
#define D 64
#define DV 16                       // float4 chunks per 64-float node row
#define N_NODES (NUM_USERS + NUM_ITEMS)
#define N_EDGES 500000
#define NNZ_G 1000000
#define NNZ_GX 2000000
#define N_GXE (NNZ_GX * 2)          // endpoint contributions (user+item halves)
#define BATCH 8192

// ---- static device scratch (no allocation allowed) ----
__device__ float g_A[(size_t)N_NODES * D];    // current node embeddings
__device__ float g_B[(size_t)N_NODES * D];    // G * A (post g-spmm)
__device__ float g_acc[(size_t)N_NODES * D];  // sum of per-layer embeddings
__device__ float g_deg[N_NODES];

// CSR-by-destination for the fused edge pipeline (gx)
__device__ int      g_cnt[N_NODES];
__device__ int      g_off[N_NODES + 1];
__device__ int      g_cur[N_NODES];
__device__ int2     g_gxe[N_GXE];             // {src | cidx<<17, val bits}
__device__ unsigned g_dst[NNZ_GX];            // packed (tu[gxr] | ti[gxr]<<16), UNSIGNED

// CSR-by-destination for the node-graph spmm (g)
__device__ int  g_gcnt[N_NODES];
__device__ int  g_goff[N_NODES + 1];
__device__ int  g_gcur[N_NODES];
__device__ int2 g_ge[NNZ_G];                  // {src, val bits}

// init: A = concat(user_emb, item_emb), acc = 0, deg/cnt/gcnt = 0
__global__ void k_init(const float* __restrict__ ue, const float* __restrict__ ie) {
    int t = blockIdx.x * blockDim.x + threadIdx.x;
    if (t >= N_NODES * DV) return;
    float4 v;
    if (t < NUM_USERS * DV) v = ((const float4*)ue)[t];
    else                    v = ((const float4*)ie)[t - NUM_USERS * DV];
    ((float4*)g_A)[t]   = v;
    ((float4*)g_acc)[t] = make_float4(0.f, 0.f, 0.f, 0.f);
    if (t < N_NODES) { g_deg[t] = 0.f; g_cnt[t] = 0; g_gcnt[t] = 0; }
}

// fused counting pass: gx endpoint counts (+dst cache), g row counts, degree
__global__ void k_count(const int* __restrict__ gxr, const int* __restrict__ g_rows,
                        const int* __restrict__ tu, const int* __restrict__ ti) {
    int t = blockIdx.x * blockDim.x + threadIdx.x;
    if (t < NNZ_GX) {
        int r = gxr[t];
        int du = tu[r], tir = ti[r];
        atomicAdd(&g_cnt[du], 1);
        atomicAdd(&g_cnt[NUM_USERS + tir], 1);
        g_dst[t] = (unsigned)du | ((unsigned)tir << 16);
    }
    if (t < NNZ_G) atomicAdd(&g_gcnt[g_rows[t]], 1);
    if (t < N_EDGES) {
        atomicAdd(&g_deg[tu[t]], 1.f);
        atomicAdd(&g_deg[NUM_USERS + ti[t]], 1.f);
    }
}

// single-block exclusive scans for both CSRs
__device__ void scan_one(const int* cnt, int* off, int* cur, int n, int* ssum) {
    int tid = threadIdx.x;
    int chunk = (n + 1023) / 1024;
    int beg = tid * chunk;
    int end = beg + chunk; if (end > n) end = n; if (beg > n) beg = n;
    int s = 0;
    for (int i = beg; i < end; ++i) s += cnt[i];
    ssum[tid] = s;
    __syncthreads();
    for (int o = 1; o < 1024; o <<= 1) {
        int v = (tid >= o) ? ssum[tid - o] : 0;
        __syncthreads();
        ssum[tid] += v;
        __syncthreads();
    }
    int run = (tid == 0) ? 0 : ssum[tid - 1];
    for (int i = beg; i < end; ++i) {
        int c = cnt[i];
        off[i] = run;
        cur[i] = run;
        run += c;
    }
    if (tid == 1023) off[n] = ssum[1023];
    __syncthreads();
}
__global__ void k_scan() {
    __shared__ int ssum[1024];
    scan_one(g_cnt,  g_off,  g_cur,  N_NODES, ssum);
    scan_one(g_gcnt, g_goff, g_gcur, N_NODES, ssum);
}

// fused scatter: gx endpoint entries + g entries into destination-sorted arrays
__global__ void k_scatter(const int* __restrict__ gxc, const float* __restrict__ gxv,
                          const int* __restrict__ g_rows, const int* __restrict__ g_cols,
                          const float* __restrict__ g_vals,
                          const int* __restrict__ tu, const int* __restrict__ ti,
                          const int* __restrict__ i2c) {
    int t = blockIdx.x * blockDim.x + threadIdx.x;
    if (t < NNZ_GX) {
        int c = gxc[t];
        int su = tu[c];
        int tic = ti[c];
        int cidx = i2c[tic];
        int vb = __float_as_int(gxv[t]);
        unsigned d = g_dst[t];
        int du = (int)(d & 0xFFFFu);
        int di = NUM_USERS + (int)(d >> 16);
        int pu = atomicAdd(&g_cur[du], 1);
        g_gxe[pu] = make_int2(su | (cidx << 17), vb);
        int pi = atomicAdd(&g_cur[di], 1);
        g_gxe[pi] = make_int2((NUM_USERS + tic) | (cidx << 17), vb);
    }
    if (t < NNZ_G) {
        int p = atomicAdd(&g_gcur[g_rows[t]], 1);
        g_ge[p] = make_int2(g_cols[t], __float_as_int(g_vals[t]));
    }
}

// pull-mode node spmm: B[n] = sum_{e in seg(n)} v_e * A[src_e]  (2-way unrolled)
__global__ void __launch_bounds__(256) k_spmm_pull() {
    int t = blockIdx.x * blockDim.x + threadIdx.x;
    if (t >= N_NODES * DV) return;
    int n = t >> 4, j = t & 15;
    int i = g_goff[n], end = g_goff[n + 1];
    const float4* Av = (const float4*)g_A;
    float4 a0 = make_float4(0.f, 0.f, 0.f, 0.f);
    float4 a1 = make_float4(0.f, 0.f, 0.f, 0.f);
    for (; i + 2 <= end; i += 2) {
        int2 e0 = g_ge[i];
        int2 e1 = g_ge[i + 1];
        float v0 = __int_as_float(e0.y);
        float v1 = __int_as_float(e1.y);
        float4 x0 = Av[e0.x * DV + j];
        float4 x1 = Av[e1.x * DV + j];
        a0.x += v0 * x0.x; a0.y += v0 * x0.y; a0.z += v0 * x0.z; a0.w += v0 * x0.w;
        a1.x += v1 * x1.x; a1.y += v1 * x1.y; a1.z += v1 * x1.z; a1.w += v1 * x1.w;
    }
    if (i < end) {
        int2 e = g_ge[i];
        float v = __int_as_float(e.y);
        float4 x = Av[e.x * DV + j];
        a0.x += v * x.x; a0.y += v * x.y; a0.z += v * x.z; a0.w += v * x.w;
    }
    a0.x += a1.x; a0.y += a1.y; a0.z += a1.z; a0.w += a1.w;
    ((float4*)g_B)[t] = a0;
}

// pull-mode fused edge pipeline + combine (2-way unrolled):
//   U[n] = sum_{e in seg(n)} v_e * (B[src_e] (+ cat[cidx_e, half(n)] on layer 0))
//   A[n] = 0.5 * (U[n]/(deg[n]+1e-9) + B[n]);  acc += A
template <int LAYER0>
__global__ void __launch_bounds__(256) k_gx_pull(const float* __restrict__ cat) {
    int t = blockIdx.x * blockDim.x + threadIdx.x;
    if (t >= N_NODES * DV) return;
    int n = t >> 4, j = t & 15;
    int i = g_off[n], end = g_off[n + 1];
    const float4* Bv = (const float4*)g_B;
    const float4* catv = (const float4*)cat;
    int coff = ((n >= NUM_USERS) ? 16 : 0) + j;   // cat half select by destination
    float4 a0 = make_float4(0.f, 0.f, 0.f, 0.f);
    float4 a1 = make_float4(0.f, 0.f, 0.f, 0.f);
    for (; i + 2 <= end; i += 2) {
        int2 e0 = g_gxe[i];
        int2 e1 = g_gxe[i + 1];
        float v0 = __int_as_float(e0.y);
        float v1 = __int_as_float(e1.y);
        float4 x0 = Bv[(e0.x & 0x1FFFF) * DV + j];
        float4 x1 = Bv[(e1.x & 0x1FFFF) * DV + j];
        if (LAYER0) {
            float4 c0 = catv[((e0.x >> 17) & 0x1FF) * 32 + coff];
            float4 c1 = catv[((e1.x >> 17) & 0x1FF) * 32 + coff];
            x0.x += c0.x; x0.y += c0.y; x0.z += c0.z; x0.w += c0.w;
            x1.x += c1.x; x1.y += c1.y; x1.z += c1.z; x1.w += c1.w;
        }
        a0.x += v0 * x0.x; a0.y += v0 * x0.y; a0.z += v0 * x0.z; a0.w += v0 * x0.w;
        a1.x += v1 * x1.x; a1.y += v1 * x1.y; a1.z += v1 * x1.z; a1.w += v1 * x1.w;
    }
    if (i < end) {
        int2 e = g_gxe[i];
        float v = __int_as_float(e.y);
        float4 x = Bv[(e.x & 0x1FFFF) * DV + j];
        if (LAYER0) {
            float4 c = catv[((e.x >> 17) & 0x1FF) * 32 + coff];
            x.x += c.x; x.y += c.y; x.z += c.z; x.w += c.w;
        }
        a0.x += v * x.x; a0.y += v * x.y; a0.z += v * x.z; a0.w += v * x.w;
    }
    a0.x += a1.x; a0.y += a1.y; a0.z += a1.z; a0.w += a1.w;
    float inv = 0.5f / (g_deg[n] + 1e-9f);
    float4 b = Bv[t];
    float4 a;
    a.x = a0.x * inv + 0.5f * b.x;
    a.y = a0.y * inv + 0.5f * b.y;
    a.z = a0.z * inv + 0.5f * b.z;
    a.w = a0.w * inv + 0.5f * b.w;
    ((float4*)g_A)[t] = a;
    float4 ac = ((float4*)g_acc)[t];
    ac.x += a.x; ac.y += a.y; ac.z += a.z; ac.w += a.w;
    ((float4*)g_acc)[t] = ac;
}

// gamma[b] = dot(acc[users[b]], acc[50000+items[b]]) / 9   (mean over 3 layers)
__global__ void k_dot(const int* __restrict__ users, const int* __restrict__ items,
                      float* __restrict__ out) {
    int t = blockIdx.x * blockDim.x + threadIdx.x;
    int b = t >> 5;
    if (b >= BATCH) return;
    int lane = t & 31;
    const float2* au = (const float2*)(g_acc + (size_t)users[b] * D);
    const float2* ai = (const float2*)(g_acc + (size_t)(NUM_USERS + items[b]) * D);
    float2 x = au[lane], y = ai[lane];
    float s = x.x * y.x + x.y * y.y;
    #pragma unroll
    for (int o = 16; o; o >>= 1) s += __shfl_down_sync(0xffffffffu, s, o);
    if (lane == 0) out[b] = s * (1.f / 9.f);
}

extern "C" void kernel_launch(void* const* d_in, const int* in_sizes, int n_in,
                              void* d_out, int out_size) {
    const float* user_emb = (const float*)d_in[0];
    const float* item_emb = (const float*)d_in[1];
    const float* cat_emb  = (const float*)d_in[2];
    const float* g_vals   = (const float*)d_in[3];
    const float* gx_vals  = (const float*)d_in[4];
    const int*   g_rows   = (const int*)d_in[5];
    const int*   g_cols   = (const int*)d_in[6];
    const int*   gx_rows  = (const int*)d_in[7];
    const int*   gx_cols  = (const int*)d_in[8];
    const int*   tu       = (const int*)d_in[9];
    const int*   ti       = (const int*)d_in[10];
    const int*   i2c      = (const int*)d_in[11];
    const int*   users    = (const int*)d_in[12];
    const int*   items    = (const int*)d_in[13];
    float* out = (float*)d_out;

    const int TB = 256;
    int node_grid = (N_NODES * DV + TB - 1) / TB;        // 6250
    int big_grid  = (NNZ_GX + TB - 1) / TB;              // 7813 (covers all count/scatter ranges)
    int dot_grid  = (BATCH * 32 + TB - 1) / TB;          // 1024

    // launch order chosen so ncu (-s 5 -c 1) profiles k_gx_pull<1> (launch #6)
    k_init<<<node_grid, TB>>>(user_emb, item_emb);                       // 1
    k_count<<<big_grid, TB>>>(gx_rows, g_rows, tu, ti);                  // 2
    k_scan<<<1, 1024>>>();                                               // 3
    k_scatter<<<big_grid, TB>>>(gx_cols, gx_vals, g_rows, g_cols,
                                g_vals, tu, ti, i2c);                    // 4
    k_spmm_pull<<<node_grid, TB>>>();                                    // 5
    k_gx_pull<1><<<node_grid, TB>>>(cat_emb);                            // 6  <- profiled
    for (int L = 1; L < 3; ++L) {
        k_spmm_pull<<<node_grid, TB>>>();
        k_gx_pull<0><<<node_grid, TB>>>(cat_emb);
    }
    k_dot<<<dot_grid, TB>>>(users, items, out);
}